// round 8
// baseline (speedup 1.0000x reference)
#include <cuda_runtime.h>

#define N_NODES 80000
#define N_EDGES 1280000
#define IN_CH 128
#define HID 64
#define OUT_CH 32

#define SCAN_BLK 512
#define N_SCAN_BLOCKS ((N_NODES + SCAN_BLK - 1) / SCAN_BLK)   // 157

__device__ __align__(256) float g_dinv[N_NODES];
__device__ __align__(256) int   g_cnt [N_NODES];
__device__ __align__(256) int   g_offs[N_NODES + 1];
__device__ __align__(256) int   g_cursor[N_NODES];
__device__ __align__(256) int   g_bsum[N_SCAN_BLOCKS];
__device__ __align__(256) int   g_csr [N_EDGES];
__device__ __align__(256) float g_h1s [(size_t)N_NODES * HID];     // dinv*(x@W1)
__device__ __align__(256) float g_out1[(size_t)N_NODES * HID];     // relu(b1 + ...)
__device__ __align__(256) float g_h2s [(size_t)N_NODES * OUT_CH];  // dinv*(out1@W2)

// ---------------- CSR build ----------------

__global__ void k_zero_cnt() {
    int i = blockIdx.x * blockDim.x + threadIdx.x;
    if (i < N_NODES) g_cnt[i] = 0;
}

__global__ void k_cnt(const int* __restrict__ dst) {
    int e = blockIdx.x * blockDim.x + threadIdx.x;
    if (e < N_EDGES) atomicAdd(&g_cnt[dst[e]], 1);
}

// per-block scan of counts; dinv fused (reads g_cnt anyway)
__global__ void __launch_bounds__(SCAN_BLK) k_scan1() {
    __shared__ int s[2 * SCAN_BLK];
    int t = threadIdx.x;
    int gi = blockIdx.x * SCAN_BLK + t;
    int v = (gi < N_NODES) ? g_cnt[gi] : 0;
    if (gi < N_NODES) g_dinv[gi] = rsqrtf((float)(v + 1));   // + self loop
    int* a = s; int* b = s + SCAN_BLK;
    a[t] = v;
    __syncthreads();
#pragma unroll
    for (int off = 1; off < SCAN_BLK; off <<= 1) {
        b[t] = a[t] + ((t >= off) ? a[t - off] : 0);
        int* tmp = a; a = b; b = tmp;
        __syncthreads();
    }
    if (gi < N_NODES) g_offs[gi] = a[t] - v;   // exclusive, block-local
    if (t == SCAN_BLK - 1) g_bsum[blockIdx.x] = a[t];
}

__global__ void __launch_bounds__(256) k_scan2() {
    __shared__ int s[2 * 256];
    int t = threadIdx.x;
    int v = (t < N_SCAN_BLOCKS) ? g_bsum[t] : 0;
    int* a = s; int* b = s + 256;
    a[t] = v;
    __syncthreads();
#pragma unroll
    for (int off = 1; off < 256; off <<= 1) {
        b[t] = a[t] + ((t >= off) ? a[t - off] : 0);
        int* tmp = a; a = b; b = tmp;
        __syncthreads();
    }
    if (t < N_SCAN_BLOCKS) g_bsum[t] = a[t] - v;   // exclusive
    if (t == 0) g_offs[N_NODES] = N_EDGES;
}

__global__ void k_scan3() {
    int gi = blockIdx.x * blockDim.x + threadIdx.x;
    if (gi < N_NODES) {
        int o = g_offs[gi] + g_bsum[gi / SCAN_BLK];
        g_offs[gi] = o;
        g_cursor[gi] = o;
    }
}

__global__ void k_fill(const int* __restrict__ src, const int* __restrict__ dst) {
    int e = blockIdx.x * blockDim.x + threadIdx.x;
    if (e < N_EDGES) {
        int pos = atomicAdd(&g_cursor[dst[e]], 1);
        g_csr[pos] = src[e];
    }
}

// ---------------- GEMM1: h1s = dinv * (x @ W1) (128 -> 64) ----------------
// 128 threads/block, tile 128 nodes x 64 ch, thread = 4 nodes x 16 ch.
// k-unroll 4 with xv prefetch: 16 LDS up front, 256-FMA window to hide latency.

__global__ void __launch_bounds__(128) k_gemm1(const float* __restrict__ x,
                                               const float* __restrict__ W1) {
    __shared__ float sW[32 * 64];
    __shared__ float sX[128 * 33];
    const int tn = threadIdx.x & 3;
    const int tm = threadIdx.x >> 2;
    const int cg = tn << 4;
    const int nodeBase = blockIdx.x * 128;

    float acc[4][16];
#pragma unroll
    for (int j = 0; j < 4; j++)
#pragma unroll
        for (int c = 0; c < 16; c++) acc[j][c] = 0.0f;

    for (int kt = 0; kt < IN_CH; kt += 32) {
#pragma unroll
        for (int i = threadIdx.x; i < 512; i += 128)
            ((float4*)sW)[i] =
                ((const float4*)W1)[(size_t)(kt + (i >> 4)) * 16 + (i & 15)];
#pragma unroll
        for (int i = threadIdx.x; i < 1024; i += 128) {
            int n = i >> 3, f4 = i & 7;
            float4 v = ((const float4*)x)[(size_t)(nodeBase + n) * 32 + (kt >> 2) + f4];
            float* p = sX + n * 33 + (f4 << 2);
            p[0] = v.x; p[1] = v.y; p[2] = v.z; p[3] = v.w;
        }
        __syncthreads();
#pragma unroll
        for (int k = 0; k < 32; k += 4) {
            // prefetch 4 k-steps of x values (16 scalar LDS)
            float xv[4][4];
#pragma unroll
            for (int kk = 0; kk < 4; kk++)
#pragma unroll
                for (int j = 0; j < 4; j++)
                    xv[kk][j] = sX[(tm * 4 + j) * 33 + k + kk];
#pragma unroll
            for (int kk = 0; kk < 4; kk++) {
                const float4* w4 = (const float4*)(sW + (k + kk) * 64 + cg);
                float4 w0 = w4[0], w1 = w4[1], w2 = w4[2], w3 = w4[3];
#pragma unroll
                for (int j = 0; j < 4; j++) {
                    float xj = xv[kk][j];
                    acc[j][0]  += xj * w0.x;  acc[j][1]  += xj * w0.y;
                    acc[j][2]  += xj * w0.z;  acc[j][3]  += xj * w0.w;
                    acc[j][4]  += xj * w1.x;  acc[j][5]  += xj * w1.y;
                    acc[j][6]  += xj * w1.z;  acc[j][7]  += xj * w1.w;
                    acc[j][8]  += xj * w2.x;  acc[j][9]  += xj * w2.y;
                    acc[j][10] += xj * w2.z;  acc[j][11] += xj * w2.w;
                    acc[j][12] += xj * w3.x;  acc[j][13] += xj * w3.y;
                    acc[j][14] += xj * w3.z;  acc[j][15] += xj * w3.w;
                }
            }
        }
        __syncthreads();
    }
#pragma unroll
    for (int j = 0; j < 4; j++) {
        int node = nodeBase + tm * 4 + j;
        float dj = g_dinv[node];
        float4* out = (float4*)(g_h1s + (size_t)node * HID + cg);
#pragma unroll
        for (int q = 0; q < 4; q++)
            out[q] = make_float4(dj * acc[j][4 * q], dj * acc[j][4 * q + 1],
                                 dj * acc[j][4 * q + 2], dj * acc[j][4 * q + 3]);
    }
}

// ---------------- agg1 (warp/node, lane = 2 ch, MLP-1 — proven) ----------------

__global__ void __launch_bounds__(256) k_agg1(const float* __restrict__ b1) {
    int node = blockIdx.x * 8 + (threadIdx.x >> 5);
    if (node >= N_NODES) return;
    int lane = threadIdx.x & 31;
    const float2* h = (const float2*)g_h1s;
    int beg = g_offs[node], end = g_offs[node + 1];
    float2 acc = h[(size_t)node * 32 + lane];   // self
    for (int c = beg; c < end; c += 32) {
        int idx = (c + lane < end) ? g_csr[c + lane] : 0;
        int m = min(32, end - c);
        for (int t = 0; t < m; ++t) {
            int j = __shfl_sync(0xffffffffu, idx, t);
            float2 v = h[(size_t)j * 32 + lane];
            acc.x += v.x; acc.y += v.y;
        }
    }
    float di = g_dinv[node];
    float2 bv = ((const float2*)b1)[lane];
    ((float2*)g_out1)[(size_t)node * 32 + lane] =
        make_float2(fmaxf(bv.x + di * acc.x, 0.0f),
                    fmaxf(bv.y + di * acc.y, 0.0f));
}

// ---------------- GEMM2: h2s = dinv * (out1 @ W2) (64 -> 32) ----------------

__global__ void __launch_bounds__(128) k_gemm2(const float* __restrict__ W2) {
    __shared__ float sW[64 * 32];
    __shared__ float sX[128 * 65];
    const int tn = threadIdx.x & 3;
    const int tm = threadIdx.x >> 2;
    const int cg = tn << 3;
    const int nodeBase = blockIdx.x * 128;

#pragma unroll
    for (int i = threadIdx.x; i < 512; i += 128)
        ((float4*)sW)[i] = ((const float4*)W2)[i];
#pragma unroll
    for (int i = threadIdx.x; i < 2048; i += 128) {
        int n = i >> 4, f4 = i & 15;
        float4 v = ((const float4*)g_out1)[(size_t)(nodeBase + n) * 16 + f4];
        float* p = sX + n * 65 + (f4 << 2);
        p[0] = v.x; p[1] = v.y; p[2] = v.z; p[3] = v.w;
    }
    __syncthreads();

    float acc[4][8];
#pragma unroll
    for (int j = 0; j < 4; j++)
#pragma unroll
        for (int c = 0; c < 8; c++) acc[j][c] = 0.0f;

#pragma unroll 4
    for (int k = 0; k < HID; ++k) {
        const float4* w4 = (const float4*)(sW + k * 32 + cg);
        float4 w0 = w4[0], w1 = w4[1];
        float xv[4];
#pragma unroll
        for (int j = 0; j < 4; j++) xv[j] = sX[(tm * 4 + j) * 65 + k];
#pragma unroll
        for (int j = 0; j < 4; j++) {
            acc[j][0] += xv[j] * w0.x; acc[j][1] += xv[j] * w0.y;
            acc[j][2] += xv[j] * w0.z; acc[j][3] += xv[j] * w0.w;
            acc[j][4] += xv[j] * w1.x; acc[j][5] += xv[j] * w1.y;
            acc[j][6] += xv[j] * w1.z; acc[j][7] += xv[j] * w1.w;
        }
    }
#pragma unroll
    for (int j = 0; j < 4; j++) {
        int node = nodeBase + tm * 4 + j;
        float dj = g_dinv[node];
        float4* out = (float4*)(g_h2s + (size_t)node * OUT_CH + cg);
        out[0] = make_float4(dj * acc[j][0], dj * acc[j][1],
                             dj * acc[j][2], dj * acc[j][3]);
        out[1] = make_float4(dj * acc[j][4], dj * acc[j][5],
                             dj * acc[j][6], dj * acc[j][7]);
    }
}

// ---------------- agg2 (warp/node, lane = 1 ch, MLP-1 — proven) ----------------

__global__ void __launch_bounds__(256) k_agg2(const float* __restrict__ b2,
                                              float* __restrict__ out) {
    int node = blockIdx.x * 8 + (threadIdx.x >> 5);
    if (node >= N_NODES) return;
    int lane = threadIdx.x & 31;
    int beg = g_offs[node], end = g_offs[node + 1];
    float acc = g_h2s[(size_t)node * 32 + lane];   // self
    for (int c = beg; c < end; c += 32) {
        int idx = (c + lane < end) ? g_csr[c + lane] : 0;
        int m = min(32, end - c);
        for (int t = 0; t < m; ++t) {
            int j = __shfl_sync(0xffffffffu, idx, t);
            acc += g_h2s[(size_t)j * 32 + lane];
        }
    }
    float di = g_dinv[node];
    out[(size_t)node * 32 + lane] = b2[lane] + di * acc;
}

// ---------------- launch ----------------

extern "C" void kernel_launch(void* const* d_in, const int* in_sizes, int n_in,
                              void* d_out, int out_size) {
    const float* x   = (const float*)d_in[0];
    const int*   ei  = (const int*)d_in[1];
    const float* W1  = (const float*)d_in[2];
    const float* b1  = (const float*)d_in[3];
    const float* W2  = (const float*)d_in[4];
    const float* b2  = (const float*)d_in[5];
    float*       out = (float*)d_out;

    const int* src = ei;
    const int* dst = ei + N_EDGES;

    k_zero_cnt<<<(N_NODES + 255) / 256, 256>>>();
    k_cnt     <<<(N_EDGES + 255) / 256, 256>>>(dst);
    k_scan1   <<<N_SCAN_BLOCKS, SCAN_BLK>>>();
    k_scan2   <<<1, 256>>>();
    k_scan3   <<<(N_NODES + 255) / 256, 256>>>();
    k_fill    <<<(N_EDGES + 255) / 256, 256>>>(src, dst);

    k_gemm1   <<<N_NODES / 128, 128>>>(x, W1);
    k_agg1    <<<(N_NODES + 7) / 8, 256>>>(b1);
    k_gemm2   <<<N_NODES / 128, 128>>>(W2);
    k_agg2    <<<(N_NODES + 7) / 8, 256>>>(b2, out);
}

// round 9
// speedup vs baseline: 1.0397x; 1.0397x over previous
#include <cuda_runtime.h>
#include <cuda_fp16.h>

#define N_NODES 80000
#define N_EDGES 1280000
#define IN_CH 128
#define HID 64
#define OUT_CH 32

#define SCAN_BLK 512
#define N_SCAN_BLOCKS ((N_NODES + SCAN_BLK - 1) / SCAN_BLK)   // 157

__device__ __align__(256) float  g_dinv[N_NODES];
__device__ __align__(256) int    g_cnt [N_NODES];
__device__ __align__(256) int    g_offs[N_NODES + 1];
__device__ __align__(256) int    g_cursor[N_NODES];
__device__ __align__(256) int    g_bsum[N_SCAN_BLOCKS];
__device__ __align__(256) int    g_csr [N_EDGES];
__device__ __align__(256) __half g_h1s [(size_t)N_NODES * HID];     // fp16: dinv*(x@W1)
__device__ __align__(256) float  g_out1[(size_t)N_NODES * HID];     // fp32: relu(b1+..)
__device__ __align__(256) __half g_h2s [(size_t)N_NODES * OUT_CH];  // fp16: dinv*(out1@W2)

// ---------------- CSR build ----------------

__global__ void k_zero_cnt() {
    int i = blockIdx.x * blockDim.x + threadIdx.x;
    if (i < N_NODES) g_cnt[i] = 0;
}

__global__ void k_cnt(const int* __restrict__ dst) {
    int e = blockIdx.x * blockDim.x + threadIdx.x;
    if (e < N_EDGES) atomicAdd(&g_cnt[dst[e]], 1);
}

__global__ void __launch_bounds__(SCAN_BLK) k_scan1() {
    __shared__ int s[2 * SCAN_BLK];
    int t = threadIdx.x;
    int gi = blockIdx.x * SCAN_BLK + t;
    int v = (gi < N_NODES) ? g_cnt[gi] : 0;
    if (gi < N_NODES) g_dinv[gi] = rsqrtf((float)(v + 1));   // + self loop
    int* a = s; int* b = s + SCAN_BLK;
    a[t] = v;
    __syncthreads();
#pragma unroll
    for (int off = 1; off < SCAN_BLK; off <<= 1) {
        b[t] = a[t] + ((t >= off) ? a[t - off] : 0);
        int* tmp = a; a = b; b = tmp;
        __syncthreads();
    }
    if (gi < N_NODES) g_offs[gi] = a[t] - v;
    if (t == SCAN_BLK - 1) g_bsum[blockIdx.x] = a[t];
}

__global__ void __launch_bounds__(256) k_scan2() {
    __shared__ int s[2 * 256];
    int t = threadIdx.x;
    int v = (t < N_SCAN_BLOCKS) ? g_bsum[t] : 0;
    int* a = s; int* b = s + 256;
    a[t] = v;
    __syncthreads();
#pragma unroll
    for (int off = 1; off < 256; off <<= 1) {
        b[t] = a[t] + ((t >= off) ? a[t - off] : 0);
        int* tmp = a; a = b; b = tmp;
        __syncthreads();
    }
    if (t < N_SCAN_BLOCKS) g_bsum[t] = a[t] - v;
    if (t == 0) g_offs[N_NODES] = N_EDGES;
}

__global__ void k_scan3() {
    int gi = blockIdx.x * blockDim.x + threadIdx.x;
    if (gi < N_NODES) {
        int o = g_offs[gi] + g_bsum[gi / SCAN_BLK];
        g_offs[gi] = o;
        g_cursor[gi] = o;
    }
}

__global__ void k_fill(const int* __restrict__ src, const int* __restrict__ dst) {
    int e = blockIdx.x * blockDim.x + threadIdx.x;
    if (e < N_EDGES) {
        int pos = atomicAdd(&g_cursor[dst[e]], 1);
        g_csr[pos] = src[e];
    }
}

// ---------------- GEMM1: h1s = fp16(dinv * (x @ W1)) (128 -> 64) ----------------
// Proven tiling: 128 thr/block, 128 nodes x 64 ch, thread = 4 nodes x 16 ch.

__global__ void __launch_bounds__(128) k_gemm1(const float* __restrict__ x,
                                               const float* __restrict__ W1) {
    __shared__ float sW[32 * 64];
    __shared__ float sX[128 * 33];
    const int tn = threadIdx.x & 3;
    const int tm = threadIdx.x >> 2;
    const int cg = tn << 4;
    const int nodeBase = blockIdx.x * 128;

    float acc[4][16];
#pragma unroll
    for (int j = 0; j < 4; j++)
#pragma unroll
        for (int c = 0; c < 16; c++) acc[j][c] = 0.0f;

    for (int kt = 0; kt < IN_CH; kt += 32) {
#pragma unroll
        for (int i = threadIdx.x; i < 512; i += 128)
            ((float4*)sW)[i] =
                ((const float4*)W1)[(size_t)(kt + (i >> 4)) * 16 + (i & 15)];
#pragma unroll
        for (int i = threadIdx.x; i < 1024; i += 128) {
            int n = i >> 3, f4 = i & 7;
            float4 v = ((const float4*)x)[(size_t)(nodeBase + n) * 32 + (kt >> 2) + f4];
            float* p = sX + n * 33 + (f4 << 2);
            p[0] = v.x; p[1] = v.y; p[2] = v.z; p[3] = v.w;
        }
        __syncthreads();
#pragma unroll 2
        for (int k = 0; k < 32; ++k) {
            const float4* w4 = (const float4*)(sW + k * 64 + cg);
            float4 w0 = w4[0], w1 = w4[1], w2 = w4[2], w3 = w4[3];
            float xv[4];
#pragma unroll
            for (int j = 0; j < 4; j++) xv[j] = sX[(tm * 4 + j) * 33 + k];
#pragma unroll
            for (int j = 0; j < 4; j++) {
                acc[j][0]  += xv[j] * w0.x;  acc[j][1]  += xv[j] * w0.y;
                acc[j][2]  += xv[j] * w0.z;  acc[j][3]  += xv[j] * w0.w;
                acc[j][4]  += xv[j] * w1.x;  acc[j][5]  += xv[j] * w1.y;
                acc[j][6]  += xv[j] * w1.z;  acc[j][7]  += xv[j] * w1.w;
                acc[j][8]  += xv[j] * w2.x;  acc[j][9]  += xv[j] * w2.y;
                acc[j][10] += xv[j] * w2.z;  acc[j][11] += xv[j] * w2.w;
                acc[j][12] += xv[j] * w3.x;  acc[j][13] += xv[j] * w3.y;
                acc[j][14] += xv[j] * w3.z;  acc[j][15] += xv[j] * w3.w;
            }
        }
        __syncthreads();
    }
#pragma unroll
    for (int j = 0; j < 4; j++) {
        int node = nodeBase + tm * 4 + j;
        float dj = g_dinv[node];
        __half2* out = (__half2*)(g_h1s + (size_t)node * HID + cg);
#pragma unroll
        for (int q = 0; q < 8; q++)
            out[q] = __floats2half2_rn(dj * acc[j][2 * q], dj * acc[j][2 * q + 1]);
    }
}

// ---------------- agg1 (warp/node, lane = half2 = 2 ch, MLP-1) ----------------

__global__ void __launch_bounds__(256) k_agg1(const float* __restrict__ b1) {
    int node = blockIdx.x * 8 + (threadIdx.x >> 5);
    if (node >= N_NODES) return;
    int lane = threadIdx.x & 31;
    const __half2* h = (const __half2*)g_h1s;
    int beg = g_offs[node], end = g_offs[node + 1];
    float2 acc = __half22float2(h[(size_t)node * 32 + lane]);   // self
    for (int c = beg; c < end; c += 32) {
        int idx = (c + lane < end) ? g_csr[c + lane] : 0;
        int m = min(32, end - c);
        for (int t = 0; t < m; ++t) {
            int j = __shfl_sync(0xffffffffu, idx, t);
            float2 v = __half22float2(h[(size_t)j * 32 + lane]);
            acc.x += v.x; acc.y += v.y;
        }
    }
    float di = g_dinv[node];
    float2 bv = ((const float2*)b1)[lane];
    ((float2*)g_out1)[(size_t)node * 32 + lane] =
        make_float2(fmaxf(bv.x + di * acc.x, 0.0f),
                    fmaxf(bv.y + di * acc.y, 0.0f));
}

// ---------------- GEMM2: h2s = fp16(dinv * (out1 @ W2)) (64 -> 32) ----------------

__global__ void __launch_bounds__(128) k_gemm2(const float* __restrict__ W2) {
    __shared__ float sW[64 * 32];
    __shared__ float sX[128 * 65];
    const int tn = threadIdx.x & 3;
    const int tm = threadIdx.x >> 2;
    const int cg = tn << 3;
    const int nodeBase = blockIdx.x * 128;

#pragma unroll
    for (int i = threadIdx.x; i < 512; i += 128)
        ((float4*)sW)[i] = ((const float4*)W2)[i];
#pragma unroll
    for (int i = threadIdx.x; i < 2048; i += 128) {
        int n = i >> 4, f4 = i & 15;
        float4 v = ((const float4*)g_out1)[(size_t)(nodeBase + n) * 16 + f4];
        float* p = sX + n * 65 + (f4 << 2);
        p[0] = v.x; p[1] = v.y; p[2] = v.z; p[3] = v.w;
    }
    __syncthreads();

    float acc[4][8];
#pragma unroll
    for (int j = 0; j < 4; j++)
#pragma unroll
        for (int c = 0; c < 8; c++) acc[j][c] = 0.0f;

#pragma unroll 4
    for (int k = 0; k < HID; ++k) {
        const float4* w4 = (const float4*)(sW + k * 32 + cg);
        float4 w0 = w4[0], w1 = w4[1];
        float xv[4];
#pragma unroll
        for (int j = 0; j < 4; j++) xv[j] = sX[(tm * 4 + j) * 65 + k];
#pragma unroll
        for (int j = 0; j < 4; j++) {
            acc[j][0] += xv[j] * w0.x; acc[j][1] += xv[j] * w0.y;
            acc[j][2] += xv[j] * w0.z; acc[j][3] += xv[j] * w0.w;
            acc[j][4] += xv[j] * w1.x; acc[j][5] += xv[j] * w1.y;
            acc[j][6] += xv[j] * w1.z; acc[j][7] += xv[j] * w1.w;
        }
    }
#pragma unroll
    for (int j = 0; j < 4; j++) {
        int node = nodeBase + tm * 4 + j;
        float dj = g_dinv[node];
        __half2* out = (__half2*)(g_h2s + (size_t)node * OUT_CH + cg);
#pragma unroll
        for (int q = 0; q < 4; q++)
            out[q] = __floats2half2_rn(dj * acc[j][2 * q], dj * acc[j][2 * q + 1]);
    }
}

// ---------------- agg2 (warp/node, lane = 1 ch fp16, MLP-1) ----------------

__global__ void __launch_bounds__(256) k_agg2(const float* __restrict__ b2,
                                              float* __restrict__ out) {
    int node = blockIdx.x * 8 + (threadIdx.x >> 5);
    if (node >= N_NODES) return;
    int lane = threadIdx.x & 31;
    int beg = g_offs[node], end = g_offs[node + 1];
    float acc = __half2float(g_h2s[(size_t)node * 32 + lane]);   // self
    for (int c = beg; c < end; c += 32) {
        int idx = (c + lane < end) ? g_csr[c + lane] : 0;
        int m = min(32, end - c);
        for (int t = 0; t < m; ++t) {
            int j = __shfl_sync(0xffffffffu, idx, t);
            acc += __half2float(g_h2s[(size_t)j * 32 + lane]);
        }
    }
    float di = g_dinv[node];
    out[(size_t)node * 32 + lane] = b2[lane] + di * acc;
}

// ---------------- launch ----------------

extern "C" void kernel_launch(void* const* d_in, const int* in_sizes, int n_in,
                              void* d_out, int out_size) {
    const float* x   = (const float*)d_in[0];
    const int*   ei  = (const int*)d_in[1];
    const float* W1  = (const float*)d_in[2];
    const float* b1  = (const float*)d_in[3];
    const float* W2  = (const float*)d_in[4];
    const float* b2  = (const float*)d_in[5];
    float*       out = (float*)d_out;

    const int* src = ei;
    const int* dst = ei + N_EDGES;

    k_zero_cnt<<<(N_NODES + 255) / 256, 256>>>();
    k_cnt     <<<(N_EDGES + 255) / 256, 256>>>(dst);
    k_scan1   <<<N_SCAN_BLOCKS, SCAN_BLK>>>();
    k_scan2   <<<1, 256>>>();
    k_scan3   <<<(N_NODES + 255) / 256, 256>>>();
    k_fill    <<<(N_EDGES + 255) / 256, 256>>>(src, dst);

    k_gemm1   <<<N_NODES / 128, 128>>>(x, W1);
    k_agg1    <<<(N_NODES + 7) / 8, 256>>>(b1);
    k_gemm2   <<<N_NODES / 128, 128>>>(W2);
    k_agg2    <<<(N_NODES + 7) / 8, 256>>>(b2, out);
}

// round 10
// speedup vs baseline: 1.3745x; 1.3220x over previous
#include <cuda_runtime.h>
#include <cuda_fp16.h>

#define N_NODES 80000
#define N_EDGES 1280000
#define IN_CH 128
#define HID 64
#define OUT_CH 32

#define SCAN_BLK 512
#define N_SCAN_BLOCKS ((N_NODES + SCAN_BLK - 1) / SCAN_BLK)   // 157

__device__ __align__(256) float  g_dinv[N_NODES];
__device__ __align__(256) int    g_cnt [N_NODES];
__device__ __align__(256) int    g_offs[N_NODES + 1];
__device__ __align__(256) int    g_cursor[N_NODES];
__device__ __align__(256) int    g_bsum[N_SCAN_BLOCKS];
__device__ __align__(256) int    g_csr [N_EDGES];
__device__ __align__(256) __half g_h1s [(size_t)N_NODES * HID];     // fp16: dinv*(x@W1)
__device__ __align__(256) float  g_out1[(size_t)N_NODES * HID];     // fp32: relu(b1+..)
__device__ __align__(256) __half g_h2s [(size_t)N_NODES * OUT_CH];  // fp16: dinv*(out1@W2)

// ---------------- CSR build ----------------

__global__ void k_zero_cnt() {
    int i = blockIdx.x * blockDim.x + threadIdx.x;
    if (i < N_NODES) g_cnt[i] = 0;
}

__global__ void k_cnt(const int* __restrict__ dst) {
    int e = blockIdx.x * blockDim.x + threadIdx.x;
    if (e < N_EDGES) atomicAdd(&g_cnt[dst[e]], 1);
}

__global__ void __launch_bounds__(SCAN_BLK) k_scan1() {
    __shared__ int s[2 * SCAN_BLK];
    int t = threadIdx.x;
    int gi = blockIdx.x * SCAN_BLK + t;
    int v = (gi < N_NODES) ? g_cnt[gi] : 0;
    if (gi < N_NODES) g_dinv[gi] = rsqrtf((float)(v + 1));   // + self loop
    int* a = s; int* b = s + SCAN_BLK;
    a[t] = v;
    __syncthreads();
#pragma unroll
    for (int off = 1; off < SCAN_BLK; off <<= 1) {
        b[t] = a[t] + ((t >= off) ? a[t - off] : 0);
        int* tmp = a; a = b; b = tmp;
        __syncthreads();
    }
    if (gi < N_NODES) g_offs[gi] = a[t] - v;
    if (t == SCAN_BLK - 1) g_bsum[blockIdx.x] = a[t];
}

__global__ void __launch_bounds__(256) k_scan2() {
    __shared__ int s[2 * 256];
    int t = threadIdx.x;
    int v = (t < N_SCAN_BLOCKS) ? g_bsum[t] : 0;
    int* a = s; int* b = s + 256;
    a[t] = v;
    __syncthreads();
#pragma unroll
    for (int off = 1; off < 256; off <<= 1) {
        b[t] = a[t] + ((t >= off) ? a[t - off] : 0);
        int* tmp = a; a = b; b = tmp;
        __syncthreads();
    }
    if (t < N_SCAN_BLOCKS) g_bsum[t] = a[t] - v;
    if (t == 0) g_offs[N_NODES] = N_EDGES;
}

__global__ void k_scan3() {
    int gi = blockIdx.x * blockDim.x + threadIdx.x;
    if (gi < N_NODES) {
        int o = g_offs[gi] + g_bsum[gi / SCAN_BLK];
        g_offs[gi] = o;
        g_cursor[gi] = o;
    }
}

__global__ void k_fill(const int* __restrict__ src, const int* __restrict__ dst) {
    int e = blockIdx.x * blockDim.x + threadIdx.x;
    if (e < N_EDGES) {
        int pos = atomicAdd(&g_cursor[dst[e]], 1);
        g_csr[pos] = src[e];
    }
}

// ---------------- GEMM1 (tensor core): h1s = fp16(dinv * (x @ W1)) ----------------
// 256 thr / 8 warps. Tile 128 nodes x 64 ch. K=128 in two 64-chunks.
// Warp = one 16-row M-strip; mma.sync.m16n8k16 f16 in, f32 acc.

#define SA_STRIDE 72   // halfs; 36 words = 4 mod 32 -> ldmatrix conflict-free
#define SB_STRIDE 72

__device__ __forceinline__ unsigned smem_u32(const void* p) {
    return (unsigned)__cvta_generic_to_shared(p);
}

__global__ void __launch_bounds__(256) k_gemm1(const float* __restrict__ x,
                                               const float* __restrict__ W1) {
    __shared__ __half sA[128 * SA_STRIDE];   // 18 KB: x chunk  [node][k-local]
    __shared__ __half sB[128 * SB_STRIDE];   // 18 KB: W1 full  [k][ch]
    const int tid  = threadIdx.x;
    const int wid  = tid >> 5;
    const int lane = tid & 31;
    const int nodeBase = blockIdx.x * 128;
    const int m0 = wid * 16;

    // load full W1 (128x64 f32 -> f16), once
#pragma unroll
    for (int i = tid; i < 2048; i += 256) {           // 2048 float4
        int k = i >> 4, f4 = i & 15;
        float4 v = ((const float4*)W1)[(size_t)k * 16 + f4];
        __half2* p = (__half2*)(sB + k * SB_STRIDE + f4 * 4);
        p[0] = __floats2half2_rn(v.x, v.y);
        p[1] = __floats2half2_rn(v.z, v.w);
    }

    float acc[8][4];
#pragma unroll
    for (int n = 0; n < 8; n++)
#pragma unroll
        for (int q = 0; q < 4; q++) acc[n][q] = 0.0f;

    for (int kt = 0; kt < IN_CH; kt += 64) {
        __syncthreads();
        // load x chunk 128x64 f32 -> f16
#pragma unroll
        for (int i = tid; i < 2048; i += 256) {       // 2048 float4
            int r = i >> 4, f4 = i & 15;
            float4 v = ((const float4*)x)[(size_t)(nodeBase + r) * 32 + (kt >> 2) + f4];
            __half2* p = (__half2*)(sA + r * SA_STRIDE + f4 * 4);
            p[0] = __floats2half2_rn(v.x, v.y);
            p[1] = __floats2half2_rn(v.z, v.w);
        }
        __syncthreads();

#pragma unroll
        for (int kk = 0; kk < 4; kk++) {              // 4 x K16 steps
            int k0 = kk * 16;
            // A fragment: ldmatrix.x4 on 16x16 at (m0, k0)
            unsigned a0, a1, a2, a3;
            {
                unsigned addr = smem_u32(sA + (m0 + (lane & 15)) * SA_STRIDE
                                            + k0 + (lane >> 4) * 8);
                asm volatile(
                    "ldmatrix.sync.aligned.m8n8.x4.shared.b16 {%0,%1,%2,%3}, [%4];"
                    : "=r"(a0), "=r"(a1), "=r"(a2), "=r"(a3) : "r"(addr));
            }
#pragma unroll
            for (int n = 0; n < 8; n++) {             // 8 N-tiles of 8
                unsigned b0, b1;
                unsigned baddr = smem_u32(sB + (kt + k0 + (lane & 15)) * SB_STRIDE
                                             + n * 8);
                asm volatile(
                    "ldmatrix.sync.aligned.m8n8.x2.trans.shared.b16 {%0,%1}, [%2];"
                    : "=r"(b0), "=r"(b1) : "r"(baddr));
                asm volatile(
                    "mma.sync.aligned.m16n8k16.row.col.f32.f16.f16.f32 "
                    "{%0,%1,%2,%3}, {%4,%5,%6,%7}, {%8,%9}, {%0,%1,%2,%3};"
                    : "+f"(acc[n][0]), "+f"(acc[n][1]),
                      "+f"(acc[n][2]), "+f"(acc[n][3])
                    : "r"(a0), "r"(a1), "r"(a2), "r"(a3), "r"(b0), "r"(b1));
            }
        }
    }

    // epilogue: dinv scale, fp16 store.
    // c0,c1 -> row t/4, cols (t%4)*2+{0,1}; c2,c3 -> row t/4+8.
    int r0 = nodeBase + m0 + (lane >> 2);
    int r1 = r0 + 8;
    float d0 = g_dinv[r0], d1 = g_dinv[r1];
    int cbase = (lane & 3);   // half2 index within 8-col tile
#pragma unroll
    for (int n = 0; n < 8; n++) {
        ((__half2*)g_h1s)[(size_t)r0 * 32 + n * 4 + cbase] =
            __floats2half2_rn(d0 * acc[n][0], d0 * acc[n][1]);
        ((__half2*)g_h1s)[(size_t)r1 * 32 + n * 4 + cbase] =
            __floats2half2_rn(d1 * acc[n][2], d1 * acc[n][3]);
    }
}

// ---------------- agg1 (warp/node, lane = half2 = 2 ch, MLP-1 — proven) --------

__global__ void __launch_bounds__(256) k_agg1(const float* __restrict__ b1) {
    int node = blockIdx.x * 8 + (threadIdx.x >> 5);
    if (node >= N_NODES) return;
    int lane = threadIdx.x & 31;
    const __half2* h = (const __half2*)g_h1s;
    int beg = g_offs[node], end = g_offs[node + 1];
    float2 acc = __half22float2(h[(size_t)node * 32 + lane]);   // self
    for (int c = beg; c < end; c += 32) {
        int idx = (c + lane < end) ? g_csr[c + lane] : 0;
        int m = min(32, end - c);
        for (int t = 0; t < m; ++t) {
            int j = __shfl_sync(0xffffffffu, idx, t);
            float2 v = __half22float2(h[(size_t)j * 32 + lane]);
            acc.x += v.x; acc.y += v.y;
        }
    }
    float di = g_dinv[node];
    float2 bv = ((const float2*)b1)[lane];
    ((float2*)g_out1)[(size_t)node * 32 + lane] =
        make_float2(fmaxf(bv.x + di * acc.x, 0.0f),
                    fmaxf(bv.y + di * acc.y, 0.0f));
}

// ---------------- GEMM2 (SIMT, proven): h2s = fp16(dinv * (out1 @ W2)) ---------

__global__ void __launch_bounds__(128) k_gemm2(const float* __restrict__ W2) {
    __shared__ float sW[64 * 32];
    __shared__ float sX[128 * 65];
    const int tn = threadIdx.x & 3;
    const int tm = threadIdx.x >> 2;
    const int cg = tn << 3;
    const int nodeBase = blockIdx.x * 128;

#pragma unroll
    for (int i = threadIdx.x; i < 512; i += 128)
        ((float4*)sW)[i] = ((const float4*)W2)[i];
#pragma unroll
    for (int i = threadIdx.x; i < 2048; i += 128) {
        int n = i >> 4, f4 = i & 15;
        float4 v = ((const float4*)g_out1)[(size_t)(nodeBase + n) * 16 + f4];
        float* p = sX + n * 65 + (f4 << 2);
        p[0] = v.x; p[1] = v.y; p[2] = v.z; p[3] = v.w;
    }
    __syncthreads();

    float acc[4][8];
#pragma unroll
    for (int j = 0; j < 4; j++)
#pragma unroll
        for (int c = 0; c < 8; c++) acc[j][c] = 0.0f;

#pragma unroll 4
    for (int k = 0; k < HID; ++k) {
        const float4* w4 = (const float4*)(sW + k * 32 + cg);
        float4 w0 = w4[0], w1 = w4[1];
        float xv[4];
#pragma unroll
        for (int j = 0; j < 4; j++) xv[j] = sX[(tm * 4 + j) * 65 + k];
#pragma unroll
        for (int j = 0; j < 4; j++) {
            acc[j][0] += xv[j] * w0.x; acc[j][1] += xv[j] * w0.y;
            acc[j][2] += xv[j] * w0.z; acc[j][3] += xv[j] * w0.w;
            acc[j][4] += xv[j] * w1.x; acc[j][5] += xv[j] * w1.y;
            acc[j][6] += xv[j] * w1.z; acc[j][7] += xv[j] * w1.w;
        }
    }
#pragma unroll
    for (int j = 0; j < 4; j++) {
        int node = nodeBase + tm * 4 + j;
        float dj = g_dinv[node];
        __half2* out = (__half2*)(g_h2s + (size_t)node * OUT_CH + cg);
#pragma unroll
        for (int q = 0; q < 4; q++)
            out[q] = __floats2half2_rn(dj * acc[j][2 * q], dj * acc[j][2 * q + 1]);
    }
}

// ---------------- agg2 (warp/node, lane = 1 ch fp16, MLP-1 — proven) -----------

__global__ void __launch_bounds__(256) k_agg2(const float* __restrict__ b2,
                                              float* __restrict__ out) {
    int node = blockIdx.x * 8 + (threadIdx.x >> 5);
    if (node >= N_NODES) return;
    int lane = threadIdx.x & 31;
    int beg = g_offs[node], end = g_offs[node + 1];
    float acc = __half2float(g_h2s[(size_t)node * 32 + lane]);   // self
    for (int c = beg; c < end; c += 32) {
        int idx = (c + lane < end) ? g_csr[c + lane] : 0;
        int m = min(32, end - c);
        for (int t = 0; t < m; ++t) {
            int j = __shfl_sync(0xffffffffu, idx, t);
            acc += __half2float(g_h2s[(size_t)j * 32 + lane]);
        }
    }
    float di = g_dinv[node];
    out[(size_t)node * 32 + lane] = b2[lane] + di * acc;
}

// ---------------- launch ----------------

extern "C" void kernel_launch(void* const* d_in, const int* in_sizes, int n_in,
                              void* d_out, int out_size) {
    const float* x   = (const float*)d_in[0];
    const int*   ei  = (const int*)d_in[1];
    const float* W1  = (const float*)d_in[2];
    const float* b1  = (const float*)d_in[3];
    const float* W2  = (const float*)d_in[4];
    const float* b2  = (const float*)d_in[5];
    float*       out = (float*)d_out;

    const int* src = ei;
    const int* dst = ei + N_EDGES;

    k_zero_cnt<<<(N_NODES + 255) / 256, 256>>>();
    k_cnt     <<<(N_EDGES + 255) / 256, 256>>>(dst);
    k_scan1   <<<N_SCAN_BLOCKS, SCAN_BLK>>>();
    k_scan2   <<<1, 256>>>();
    k_scan3   <<<(N_NODES + 255) / 256, 256>>>();
    k_fill    <<<(N_EDGES + 255) / 256, 256>>>(src, dst);

    k_gemm1   <<<N_NODES / 128, 256>>>(x, W1);
    k_agg1    <<<(N_NODES + 7) / 8, 256>>>(b1);
    k_gemm2   <<<N_NODES / 128, 128>>>(W2);
    k_agg2    <<<(N_NODES + 7) / 8, 256>>>(b2, out);
}

// round 11
// speedup vs baseline: 1.5071x; 1.0964x over previous
#include <cuda_runtime.h>
#include <cuda_fp16.h>

#define N_NODES 80000
#define N_EDGES 1280000
#define IN_CH 128
#define HID 64
#define OUT_CH 32

#define SCAN_BLK 512
#define N_SCAN_BLOCKS ((N_NODES + SCAN_BLK - 1) / SCAN_BLK)   // 157

__device__ __align__(256) float  g_dinv[N_NODES];
__device__ __align__(256) int    g_cnt [N_NODES];
__device__ __align__(256) int    g_offs[N_NODES + 1];
__device__ __align__(256) int    g_cursor[N_NODES];
__device__ __align__(256) int    g_bsum[N_SCAN_BLOCKS];
__device__ __align__(256) int    g_csr [N_EDGES];
__device__ __align__(256) __half g_h1s [(size_t)N_NODES * HID];     // fp16: dinv*(x@W1)
__device__ __align__(256) __half g_out1[(size_t)N_NODES * HID];     // fp16: relu(b1+..)
__device__ __align__(256) __half g_h2s [(size_t)N_NODES * OUT_CH];  // fp16: dinv*(out1@W2)

// ---------------- CSR build ----------------

__global__ void k_cnt(const int* __restrict__ dst) {
    int e = blockIdx.x * blockDim.x + threadIdx.x;
    if (e < N_EDGES) atomicAdd(&g_cnt[dst[e]], 1);
}

__global__ void __launch_bounds__(SCAN_BLK) k_scan1() {
    __shared__ int s[2 * SCAN_BLK];
    int t = threadIdx.x;
    int gi = blockIdx.x * SCAN_BLK + t;
    int v = (gi < N_NODES) ? g_cnt[gi] : 0;
    if (gi < N_NODES) g_dinv[gi] = rsqrtf((float)(v + 1));   // + self loop
    int* a = s; int* b = s + SCAN_BLK;
    a[t] = v;
    __syncthreads();
#pragma unroll
    for (int off = 1; off < SCAN_BLK; off <<= 1) {
        b[t] = a[t] + ((t >= off) ? a[t - off] : 0);
        int* tmp = a; a = b; b = tmp;
        __syncthreads();
    }
    if (gi < N_NODES) g_offs[gi] = a[t] - v;
    if (t == SCAN_BLK - 1) g_bsum[blockIdx.x] = a[t];
}

__global__ void __launch_bounds__(256) k_scan2() {
    __shared__ int s[2 * 256];
    int t = threadIdx.x;
    int v = (t < N_SCAN_BLOCKS) ? g_bsum[t] : 0;
    int* a = s; int* b = s + 256;
    a[t] = v;
    __syncthreads();
#pragma unroll
    for (int off = 1; off < 256; off <<= 1) {
        b[t] = a[t] + ((t >= off) ? a[t - off] : 0);
        int* tmp = a; a = b; b = tmp;
        __syncthreads();
    }
    if (t < N_SCAN_BLOCKS) g_bsum[t] = a[t] - v;
    if (t == 0) g_offs[N_NODES] = N_EDGES;
}

__global__ void k_scan3() {
    int gi = blockIdx.x * blockDim.x + threadIdx.x;
    if (gi < N_NODES) {
        int o = g_offs[gi] + g_bsum[gi / SCAN_BLK];
        g_offs[gi] = o;
        g_cursor[gi] = o;
    }
}

// fill CSR; also re-zero g_cnt for the next replay (g_cnt only read by k_scan1,
// which precedes this kernel — invariant: g_cnt is all-zero at kernel_launch entry,
// true initially from .bss zero-init and restored here every call).
__global__ void k_fill(const int* __restrict__ src, const int* __restrict__ dst) {
    int e = blockIdx.x * blockDim.x + threadIdx.x;
    if (e < N_NODES) g_cnt[e] = 0;
    if (e < N_EDGES) {
        int pos = atomicAdd(&g_cursor[dst[e]], 1);
        g_csr[pos] = src[e];
    }
}

// ---------------- GEMM1 (HMMA): h1s = fp16(dinv * (x @ W1)) --------------------
// 256 thr / 8 warps. Tile 128 nodes x 64 ch. K=128 in two 64-chunks. Proven R10.

#define SA_STRIDE 72   // halfs; ldmatrix rows hit words 4r mod 32 -> conflict-free
#define SB_STRIDE 72

__device__ __forceinline__ unsigned smem_u32(const void* p) {
    return (unsigned)__cvta_generic_to_shared(p);
}

__global__ void __launch_bounds__(256) k_gemm1(const float* __restrict__ x,
                                               const float* __restrict__ W1) {
    __shared__ __half sA[128 * SA_STRIDE];
    __shared__ __half sB[128 * SB_STRIDE];
    const int tid  = threadIdx.x;
    const int wid  = tid >> 5;
    const int lane = tid & 31;
    const int nodeBase = blockIdx.x * 128;
    const int m0 = wid * 16;

#pragma unroll
    for (int i = tid; i < 2048; i += 256) {
        int k = i >> 4, f4 = i & 15;
        float4 v = ((const float4*)W1)[(size_t)k * 16 + f4];
        __half2* p = (__half2*)(sB + k * SB_STRIDE + f4 * 4);
        p[0] = __floats2half2_rn(v.x, v.y);
        p[1] = __floats2half2_rn(v.z, v.w);
    }

    float acc[8][4];
#pragma unroll
    for (int n = 0; n < 8; n++)
#pragma unroll
        for (int q = 0; q < 4; q++) acc[n][q] = 0.0f;

    for (int kt = 0; kt < IN_CH; kt += 64) {
        __syncthreads();
#pragma unroll
        for (int i = tid; i < 2048; i += 256) {
            int r = i >> 4, f4 = i & 15;
            float4 v = ((const float4*)x)[(size_t)(nodeBase + r) * 32 + (kt >> 2) + f4];
            __half2* p = (__half2*)(sA + r * SA_STRIDE + f4 * 4);
            p[0] = __floats2half2_rn(v.x, v.y);
            p[1] = __floats2half2_rn(v.z, v.w);
        }
        __syncthreads();

#pragma unroll
        for (int kk = 0; kk < 4; kk++) {
            int k0 = kk * 16;
            unsigned a0, a1, a2, a3;
            {
                unsigned addr = smem_u32(sA + (m0 + (lane & 15)) * SA_STRIDE
                                            + k0 + (lane >> 4) * 8);
                asm volatile(
                    "ldmatrix.sync.aligned.m8n8.x4.shared.b16 {%0,%1,%2,%3}, [%4];"
                    : "=r"(a0), "=r"(a1), "=r"(a2), "=r"(a3) : "r"(addr));
            }
#pragma unroll
            for (int n = 0; n < 8; n++) {
                unsigned b0, b1;
                unsigned baddr = smem_u32(sB + (kt + k0 + (lane & 15)) * SB_STRIDE
                                             + n * 8);
                asm volatile(
                    "ldmatrix.sync.aligned.m8n8.x2.trans.shared.b16 {%0,%1}, [%2];"
                    : "=r"(b0), "=r"(b1) : "r"(baddr));
                asm volatile(
                    "mma.sync.aligned.m16n8k16.row.col.f32.f16.f16.f32 "
                    "{%0,%1,%2,%3}, {%4,%5,%6,%7}, {%8,%9}, {%0,%1,%2,%3};"
                    : "+f"(acc[n][0]), "+f"(acc[n][1]),
                      "+f"(acc[n][2]), "+f"(acc[n][3])
                    : "r"(a0), "r"(a1), "r"(a2), "r"(a3), "r"(b0), "r"(b1));
            }
        }
    }

    int r0 = nodeBase + m0 + (lane >> 2);
    int r1 = r0 + 8;
    float d0 = g_dinv[r0], d1 = g_dinv[r1];
    int cbase = (lane & 3);
#pragma unroll
    for (int n = 0; n < 8; n++) {
        ((__half2*)g_h1s)[(size_t)r0 * 32 + n * 4 + cbase] =
            __floats2half2_rn(d0 * acc[n][0], d0 * acc[n][1]);
        ((__half2*)g_h1s)[(size_t)r1 * 32 + n * 4 + cbase] =
            __floats2half2_rn(d1 * acc[n][2], d1 * acc[n][3]);
    }
}

// ---------------- agg1 (warp/node, lane = half2, MLP-1) -> fp16 out1 -----------

__global__ void __launch_bounds__(256) k_agg1(const float* __restrict__ b1) {
    int node = blockIdx.x * 8 + (threadIdx.x >> 5);
    if (node >= N_NODES) return;
    int lane = threadIdx.x & 31;
    const __half2* h = (const __half2*)g_h1s;
    int beg = g_offs[node], end = g_offs[node + 1];
    float2 acc = __half22float2(h[(size_t)node * 32 + lane]);   // self
    for (int c = beg; c < end; c += 32) {
        int idx = (c + lane < end) ? g_csr[c + lane] : 0;
        int m = min(32, end - c);
        for (int t = 0; t < m; ++t) {
            int j = __shfl_sync(0xffffffffu, idx, t);
            float2 v = __half22float2(h[(size_t)j * 32 + lane]);
            acc.x += v.x; acc.y += v.y;
        }
    }
    float di = g_dinv[node];
    float2 bv = ((const float2*)b1)[lane];
    ((__half2*)g_out1)[(size_t)node * 32 + lane] =
        __floats2half2_rn(fmaxf(bv.x + di * acc.x, 0.0f),
                          fmaxf(bv.y + di * acc.y, 0.0f));
}

// ---------------- GEMM2 (HMMA): h2s = fp16(dinv * (out1 @ W2)), K=64 -----------
// 256 thr / 8 warps, tile 128 nodes x 32 ch. Warp = 16 rows x 32 ch (4 N-tiles).

#define SB2_STRIDE 40   // halfs; ldmatrix rows hit words 20r mod 32 -> distinct

__global__ void __launch_bounds__(256) k_gemm2(const float* __restrict__ W2) {
    __shared__ __half sA[128 * SA_STRIDE];   // out1 tile [node][k]
    __shared__ __half sB[64 * SB2_STRIDE];   // W2 [k][ch]
    const int tid  = threadIdx.x;
    const int wid  = tid >> 5;
    const int lane = tid & 31;
    const int nodeBase = blockIdx.x * 128;
    const int m0 = wid * 16;

    // W2: 64x32 f32 = 512 float4 -> fp16
#pragma unroll
    for (int i = tid; i < 512; i += 256) {
        int k = i >> 3, f4 = i & 7;
        float4 v = ((const float4*)W2)[i];
        __half2* p = (__half2*)(sB + k * SB2_STRIDE + f4 * 4);
        p[0] = __floats2half2_rn(v.x, v.y);
        p[1] = __floats2half2_rn(v.z, v.w);
    }
    // out1 tile: 128 rows x 64 halves = 8 uint4/row
#pragma unroll
    for (int i = tid; i < 1024; i += 256) {
        int r = i >> 3, q = i & 7;
        uint4 v = ((const uint4*)g_out1)[(size_t)(nodeBase + r) * 8 + q];
        *(uint4*)(sA + r * SA_STRIDE + q * 8) = v;
    }
    __syncthreads();

    float acc[4][4];
#pragma unroll
    for (int n = 0; n < 4; n++)
#pragma unroll
        for (int q = 0; q < 4; q++) acc[n][q] = 0.0f;

#pragma unroll
    for (int kk = 0; kk < 4; kk++) {
        int k0 = kk * 16;
        unsigned a0, a1, a2, a3;
        {
            unsigned addr = smem_u32(sA + (m0 + (lane & 15)) * SA_STRIDE
                                        + k0 + (lane >> 4) * 8);
            asm volatile(
                "ldmatrix.sync.aligned.m8n8.x4.shared.b16 {%0,%1,%2,%3}, [%4];"
                : "=r"(a0), "=r"(a1), "=r"(a2), "=r"(a3) : "r"(addr));
        }
#pragma unroll
        for (int n = 0; n < 4; n++) {
            unsigned b0, b1;
            unsigned baddr = smem_u32(sB + (k0 + (lane & 15)) * SB2_STRIDE + n * 8);
            asm volatile(
                "ldmatrix.sync.aligned.m8n8.x2.trans.shared.b16 {%0,%1}, [%2];"
                : "=r"(b0), "=r"(b1) : "r"(baddr));
            asm volatile(
                "mma.sync.aligned.m16n8k16.row.col.f32.f16.f16.f32 "
                "{%0,%1,%2,%3}, {%4,%5,%6,%7}, {%8,%9}, {%0,%1,%2,%3};"
                : "+f"(acc[n][0]), "+f"(acc[n][1]),
                  "+f"(acc[n][2]), "+f"(acc[n][3])
                : "r"(a0), "r"(a1), "r"(a2), "r"(a3), "r"(b0), "r"(b1));
        }
    }

    int r0 = nodeBase + m0 + (lane >> 2);
    int r1 = r0 + 8;
    float d0 = g_dinv[r0], d1 = g_dinv[r1];
    int cbase = (lane & 3);
#pragma unroll
    for (int n = 0; n < 4; n++) {
        ((__half2*)g_h2s)[(size_t)r0 * 16 + n * 4 + cbase] =
            __floats2half2_rn(d0 * acc[n][0], d0 * acc[n][1]);
        ((__half2*)g_h2s)[(size_t)r1 * 16 + n * 4 + cbase] =
            __floats2half2_rn(d1 * acc[n][2], d1 * acc[n][3]);
    }
}

// ---------------- agg2 (warp/node, lane = 1 ch fp16, MLP-1 — proven) -----------

__global__ void __launch_bounds__(256) k_agg2(const float* __restrict__ b2,
                                              float* __restrict__ out) {
    int node = blockIdx.x * 8 + (threadIdx.x >> 5);
    if (node >= N_NODES) return;
    int lane = threadIdx.x & 31;
    int beg = g_offs[node], end = g_offs[node + 1];
    float acc = __half2float(g_h2s[(size_t)node * 32 + lane]);   // self
    for (int c = beg; c < end; c += 32) {
        int idx = (c + lane < end) ? g_csr[c + lane] : 0;
        int m = min(32, end - c);
        for (int t = 0; t < m; ++t) {
            int j = __shfl_sync(0xffffffffu, idx, t);
            acc += __half2float(g_h2s[(size_t)j * 32 + lane]);
        }
    }
    float di = g_dinv[node];
    out[(size_t)node * 32 + lane] = b2[lane] + di * acc;
}

// ---------------- launch ----------------

extern "C" void kernel_launch(void* const* d_in, const int* in_sizes, int n_in,
                              void* d_out, int out_size) {
    const float* x   = (const float*)d_in[0];
    const int*   ei  = (const int*)d_in[1];
    const float* W1  = (const float*)d_in[2];
    const float* b1  = (const float*)d_in[3];
    const float* W2  = (const float*)d_in[4];
    const float* b2  = (const float*)d_in[5];
    float*       out = (float*)d_out;

    const int* src = ei;
    const int* dst = ei + N_EDGES;

    k_cnt   <<<(N_EDGES + 255) / 256, 256>>>(dst);
    k_scan1 <<<N_SCAN_BLOCKS, SCAN_BLK>>>();
    k_scan2 <<<1, 256>>>();
    k_scan3 <<<(N_NODES + 255) / 256, 256>>>();
    k_fill  <<<(N_EDGES + 255) / 256, 256>>>(src, dst);

    k_gemm1 <<<N_NODES / 128, 256>>>(x, W1);
    k_agg1  <<<(N_NODES + 7) / 8, 256>>>(b1);
    k_gemm2 <<<N_NODES / 128, 256>>>(W2);
    k_agg2  <<<(N_NODES + 7) / 8, 256>>>(b2, out);
}